// round 5
// baseline (speedup 1.0000x reference)
#include <cuda_runtime.h>
#include <math.h>

#define NB 128
#define ND 64
#define NL0 4096
#define NL1 2048
#define NL2 1024
#define NL3 512

typedef unsigned long long u64;

// Scratch (static device allocations allowed; cudaMalloc is not)
__device__ float g_pe[NL0 * ND];                      // 1 MB positional table
__device__ float g_wt[3][128][128];                   // repacked conv weights
__device__ float g_h1[(size_t)NB * NL1 * ND];         // 67 MB
__device__ float g_h2[(size_t)NB * NL2 * ND];         // 33.5 MB

__device__ __forceinline__ void ffma2(u64& d, u64 a, u64 b) {
    asm("fma.rn.f32x2 %0, %1, %2, %0;" : "+l"(d) : "l"(a), "l"(b));
}
__device__ __forceinline__ float unpack_sum(u64 v) {
    float lo, hi;
    asm("mov.b64 {%0,%1}, %2;" : "=f"(lo), "=f"(hi) : "l"(v));
    return lo + hi;
}

// ---------------------------------------------------------------------------
// Positional embedding table (double precision to match reference's fp32
// rounding chain exactly; avoids sinf large-arg reduction error).
// ---------------------------------------------------------------------------
__global__ void pe_kernel() {
    int idx = blockIdx.x * blockDim.x + threadIdx.x;
    if (idx >= NL0 * 32) return;
    int l = idx >> 5, i = idx & 31;
    float argf = (float)(2 * i) * (float)(-log(10000.0) / 64.0);
    float divf = (float)exp((double)argf);
    float angf = (float)l * divf;
    double ang = (double)angf;
    g_pe[l * ND + 2 * i]     = (float)sin(ang);
    g_pe[l * ND + 2 * i + 1] = (float)cos(ang);
}

// ---------------------------------------------------------------------------
// Repack c_w{s} (co, ci, kk):
//   row = kk*32 + ci/2, col = ((co&3)>>1)*64 + (co>>2)*4 + (co&1)*2 + (ci&1)
// Lane tx's 4 co x 1 ci-pair = two contiguous 16B chunks at tx*16B per half;
// LDS.128, conflict-free, (ci-even, ci-odd) adjacent for FFMA2.
// ---------------------------------------------------------------------------
__global__ void wt_kernel(const float* __restrict__ w1,
                          const float* __restrict__ w2,
                          const float* __restrict__ w3) {
    int idx = blockIdx.x * blockDim.x + threadIdx.x;
    if (idx >= 3 * 64 * 64 * 4) return;
    int s = idx / 16384;
    int rem = idx - s * 16384;          // rem = co*256 + ci*4 + kk
    int co = rem >> 8;
    int ci = (rem >> 2) & 63;
    int kk = rem & 3;
    const float* w = (s == 0) ? w1 : (s == 1) ? w2 : w3;
    int row = kk * 32 + (ci >> 1);
    int col = ((co & 3) >> 1) * 64 + (co >> 2) * 4 + (co & 1) * 2 + (ci & 1);
    g_wt[s][row][col] = w[rem];
}

// ---------------------------------------------------------------------------
// Compression stage: conv1d(64->64, k=4, s=2, p=1) -> tanh [-> LN over D].
// Persistent CTAs (1/SM). Tile = 128 out positions x 64 channels, 256 threads,
// thread micro-tile 8 pos x 4 co (f32x2-packed over the ci reduction).
// Per (kk, ci-quad): 4 w-LDS.128 + 8 x-LDS.128 -> 64 FFMA2.
// FUSE_FRONT: stage1 computes token-embedding conv + PE on the fly during the
// Xs fill (x is 2MB / L2-resident; kills the separate emb kernel + 268MB DRAM).
// ---------------------------------------------------------------------------
// smem layout (floats):
//   xsl   [272]      raw-x slice (fused front only)
//   Xs    [258*68]   input tile halo, stride 68 (16B-aligned rows)
//   Ws    [16384]    stage conv weights (repacked)
//   bsm   [64] gsm [64] lbsm [64]
//   twsm  [384] tbsm [64]   token conv weights/bias (fused only)
#define OFF_XSL  0
#define OFF_XS   272
#define OFF_WS   (272 + 258 * 68)
#define OFF_BSM  (OFF_WS + 16384)
#define OFF_GSM  (OFF_BSM + 64)
#define OFF_LBSM (OFF_GSM + 64)
#define OFF_TW   (OFF_LBSM + 64)
#define OFF_TB   (OFF_TW + 384)
#define SMEM_FLOATS (OFF_TB + 64)

template <bool HAS_LN, bool FUSE_FRONT>
__global__ void __launch_bounds__(256, 1)
stage_kernel(const float* __restrict__ in, float* __restrict__ out,
             const float* __restrict__ wt, const float* __restrict__ bias,
             const float* __restrict__ lng, const float* __restrict__ lnb,
             const float* __restrict__ pe,
             const float* __restrict__ tw3, const float* __restrict__ tb3,
             const float* __restrict__ tw5, const float* __restrict__ tb5,
             const float* __restrict__ tw7, const float* __restrict__ tb7,
             const float* __restrict__ tw9, const float* __restrict__ tb9,
             int Lin, int Lout, int numTiles) {
    extern __shared__ float smem[];
    float* xsl  = smem + OFF_XSL;
    float* Xs   = smem + OFF_XS;
    float* Ws   = smem + OFF_WS;
    float* bsm  = smem + OFF_BSM;
    float* gsm  = smem + OFF_GSM;
    float* lbsm = smem + OFF_LBSM;
    float* twsm = smem + OFF_TW;
    float* tbsm = smem + OFF_TB;

    int tid = threadIdx.x;
    {   // stage weights -> smem
        const float4* wt4 = (const float4*)wt;
        float4* Ws4 = (float4*)Ws;
        for (int i = tid; i < 4096; i += 256) Ws4[i] = wt4[i];
    }
    if (tid < 64) {
        bsm[tid] = bias[tid];
        if (HAS_LN) { gsm[tid] = lng[tid]; lbsm[tid] = lnb[tid]; }
    }
    if (FUSE_FRONT) {
        if (tid < 48)  twsm[tid]        = tw3[tid];
        if (tid < 80)  twsm[48  + tid]  = tw5[tid];
        if (tid < 112) twsm[128 + tid]  = tw7[tid];
        if (tid < 144) twsm[240 + tid]  = tw9[tid];
        if (tid < 64) {
            int g = tid & 3, j = tid >> 2;
            tbsm[tid] = (g == 0 ? tb3 : g == 1 ? tb5 : g == 2 ? tb7 : tb9)[j];
        }
    }
    __syncthreads();

    // fused-front per-thread token-conv weights (fill channel is tid&63)
    int   fc = tid & 63;
    float fw[9];
    float fb = 0.f;
    int   fpad = 0;
    if (FUSE_FRONT) {
        int fg = fc & 3, fj = fc >> 2;
        int fks = 3 + 2 * fg;
        fpad = fg + 1;
        int woff = (fg == 0 ? 0 : fg == 1 ? 48 : fg == 2 ? 128 : 240) + fj * fks;
#pragma unroll
        for (int k = 0; k < 9; ++k) fw[k] = (k < fks) ? twsm[woff + k] : 0.f;
        fb = tbsm[fc];
    }

    int tx = tid & 15, ty = tid >> 4;
    int co0 = tx * 4, p0 = ty * 8;
    int tilesPerB = Lout >> 7;

    for (int tile = blockIdx.x; tile < numTiles; tile += gridDim.x) {
        int b = tile / tilesPerB;
        int t = tile - b * tilesPerB;
        int l0 = t << 7;
        int g0 = 2 * l0 - 1;

        __syncthreads();   // protect Xs/xsl against previous iteration's readers
        if (FUSE_FRONT) {
            const float* xb = in + (size_t)b * NL0;
            for (int i = tid; i < 272; i += 256) {
                int gl = g0 - 4 + i;
                xsl[i] = (gl >= 0 && gl < NL0) ? xb[gl] : 0.f;
            }
            __syncthreads();
            for (int i = tid; i < 258 * 64; i += 256) {
                int row = i >> 6;                 // channel = fc (tid&63) every iter
                int gg = g0 + row;
                float v = 0.f;
                if (gg >= 0 && gg < NL0) {
                    v = fb;
                    int base = row + 4 - fpad;
#pragma unroll
                    for (int k = 0; k < 9; ++k) v = fmaf(fw[k], xsl[base + k], v);
                    v += __ldg(pe + (size_t)gg * ND + fc);
                }
                Xs[row * 68 + fc] = v;
            }
        } else {
            const float* inb = in + (size_t)b * Lin * ND;
            for (int i = tid; i < 258 * 64; i += 256) {
                int row = i >> 6, cc = i & 63;
                int gg = g0 + row;
                Xs[row * 68 + cc] = (gg >= 0 && gg < Lin) ? inb[(size_t)gg * 64 + cc] : 0.f;
            }
        }
        __syncthreads();

        u64 acc[8][4];
#pragma unroll
        for (int j = 0; j < 8; ++j)
#pragma unroll
            for (int i = 0; i < 4; ++i) acc[j][i] = 0ull;

#pragma unroll 1
        for (int kk = 0; kk < 4; ++kk) {
            const float* xk = Xs + (2 * p0 + kk) * 68;
            const ulonglong2* wk = (const ulonglong2*)(Ws + kk * 4096) + tx;
#pragma unroll 2
            for (int cq = 0; cq < 16; ++cq) {
                const ulonglong2* wp = wk + cq * 64;
                ulonglong2 wA0 = wp[0];    // ci-pair A: co0,co1
                ulonglong2 wA1 = wp[16];   // ci-pair A: co2,co3
                ulonglong2 wB0 = wp[32];   // ci-pair B: co0,co1
                ulonglong2 wB1 = wp[48];   // ci-pair B: co2,co3
                const float* xq = xk + cq * 4;
#pragma unroll
                for (int j = 0; j < 8; ++j) {
                    ulonglong2 xv = *(const ulonglong2*)(xq + j * 136);
                    ffma2(acc[j][0], xv.x, wA0.x);
                    ffma2(acc[j][1], xv.x, wA0.y);
                    ffma2(acc[j][2], xv.x, wA1.x);
                    ffma2(acc[j][3], xv.x, wA1.y);
                    ffma2(acc[j][0], xv.y, wB0.x);
                    ffma2(acc[j][1], xv.y, wB0.y);
                    ffma2(acc[j][2], xv.y, wB1.x);
                    ffma2(acc[j][3], xv.y, wB1.y);
                }
            }
        }

        float* outb = out + ((size_t)b * Lout + l0) * ND;
#pragma unroll
        for (int j = 0; j < 8; ++j) {
            float t0 = tanhf(unpack_sum(acc[j][0]) + bsm[co0 + 0]);
            float t1 = tanhf(unpack_sum(acc[j][1]) + bsm[co0 + 1]);
            float t2 = tanhf(unpack_sum(acc[j][2]) + bsm[co0 + 2]);
            float t3 = tanhf(unpack_sum(acc[j][3]) + bsm[co0 + 3]);
            float4 o4;
            if (HAS_LN) {
                float s1 = t0 + t1 + t2 + t3;
                float s2 = t0 * t0 + t1 * t1 + t2 * t2 + t3 * t3;
#pragma unroll
                for (int o = 1; o < 16; o <<= 1) {
                    s1 += __shfl_xor_sync(0xffffffffu, s1, o);
                    s2 += __shfl_xor_sync(0xffffffffu, s2, o);
                }
                float m   = s1 * (1.f / 64.f);
                float v   = s2 * (1.f / 64.f) - m * m;
                float inv = 1.f / sqrtf(v + 1e-5f);
                o4.x = (t0 - m) * inv * gsm[co0 + 0] + lbsm[co0 + 0];
                o4.y = (t1 - m) * inv * gsm[co0 + 1] + lbsm[co0 + 1];
                o4.z = (t2 - m) * inv * gsm[co0 + 2] + lbsm[co0 + 2];
                o4.w = (t3 - m) * inv * gsm[co0 + 3] + lbsm[co0 + 3];
            } else {
                o4.x = t0; o4.y = t1; o4.z = t2; o4.w = t3;
            }
            *(float4*)(outb + (size_t)(p0 + j) * ND + co0) = o4;
        }
    }
}

extern "C" void kernel_launch(void* const* d_in, const int* in_sizes, int n_in,
                              void* d_out, int out_size) {
    const float* x   = (const float*)d_in[0];
    const float* tw3 = (const float*)d_in[1];
    const float* tb3 = (const float*)d_in[2];
    const float* tw5 = (const float*)d_in[3];
    const float* tb5 = (const float*)d_in[4];
    const float* tw7 = (const float*)d_in[5];
    const float* tb7 = (const float*)d_in[6];
    const float* tw9 = (const float*)d_in[7];
    const float* tb9 = (const float*)d_in[8];
    const float* cw1 = (const float*)d_in[9];
    const float* cb1 = (const float*)d_in[10];
    const float* cw2 = (const float*)d_in[11];
    const float* cb2 = (const float*)d_in[12];
    const float* cw3 = (const float*)d_in[13];
    const float* cb3 = (const float*)d_in[14];
    const float* lg1 = (const float*)d_in[15];
    const float* lb1 = (const float*)d_in[16];
    const float* lg2 = (const float*)d_in[17];
    const float* lb2 = (const float*)d_in[18];
    (void)in_sizes; (void)n_in; (void)out_size;

    void *pe_p, *wt_p, *h1_p, *h2_p;
    cudaGetSymbolAddress(&pe_p, g_pe);
    cudaGetSymbolAddress(&wt_p, g_wt);
    cudaGetSymbolAddress(&h1_p, g_h1);
    cudaGetSymbolAddress(&h2_p, g_h2);
    float* pe  = (float*)pe_p;
    float* h1  = (float*)h1_p;
    float* h2  = (float*)h2_p;
    float* wtb = (float*)wt_p;

    const int smemsz = SMEM_FLOATS * 4;   // ~139 KB -> 1 CTA/SM
    cudaFuncSetAttribute((const void*)stage_kernel<true, true>,
                         cudaFuncAttributeMaxDynamicSharedMemorySize, smemsz);
    cudaFuncSetAttribute((const void*)stage_kernel<true, false>,
                         cudaFuncAttributeMaxDynamicSharedMemorySize, smemsz);
    cudaFuncSetAttribute((const void*)stage_kernel<false, false>,
                         cudaFuncAttributeMaxDynamicSharedMemorySize, smemsz);

    pe_kernel<<<(NL0 * 32 + 255) / 256, 256>>>();
    wt_kernel<<<(3 * 64 * 64 * 4 + 255) / 256, 256>>>(cw1, cw2, cw3);

    // stage1: fused token-embedding + PE front-end, reads raw x
    stage_kernel<true, true><<<148, 256, smemsz>>>(
        x, h1, wtb + 0 * 128 * 128, cb1, lg1, lb1, pe,
        tw3, tb3, tw5, tb5, tw7, tb7, tw9, tb9,
        NL0, NL1, NB * (NL1 / 128));
    stage_kernel<true, false><<<148, 256, smemsz>>>(
        h1, h2, wtb + 1 * 128 * 128, cb2, lg2, lb2, pe,
        nullptr, nullptr, nullptr, nullptr, nullptr, nullptr, nullptr, nullptr,
        NL1, NL2, NB * (NL2 / 128));
    stage_kernel<false, false><<<148, 256, smemsz>>>(
        h2, (float*)d_out, wtb + 2 * 128 * 128, cb3, nullptr, nullptr, pe,
        nullptr, nullptr, nullptr, nullptr, nullptr, nullptr, nullptr, nullptr,
        NL2, NL3, NB * (NL3 / 128));
}

// round 6
// speedup vs baseline: 1.1806x; 1.1806x over previous
#include <cuda_runtime.h>
#include <math.h>

#define NB 128
#define ND 64
#define NL0 4096
#define NL1 2048
#define NL2 1024
#define NL3 512

typedef unsigned long long u64;

// Scratch (static device allocations allowed; cudaMalloc is not)
__device__ float g_pe[NL0 * ND];                      // 1 MB positional table
__device__ float g_wt[3][128][128];                   // repacked conv weights
__device__ float g_h1[(size_t)NB * NL1 * ND];         // 67 MB
__device__ float g_h2[(size_t)NB * NL2 * ND];         // 33.5 MB

__device__ __forceinline__ void ffma2(u64& d, u64 a, u64 b) {
    asm("fma.rn.f32x2 %0, %1, %2, %0;" : "+l"(d) : "l"(a), "l"(b));
}
__device__ __forceinline__ float unpack_sum(u64 v) {
    float lo, hi;
    asm("mov.b64 {%0,%1}, %2;" : "=f"(lo), "=f"(hi) : "l"(v));
    return lo + hi;
}

// ---------------------------------------------------------------------------
// Positional embedding table (double precision to match reference's fp32
// rounding chain exactly; avoids sinf large-arg reduction error).
// ---------------------------------------------------------------------------
__global__ void pe_kernel() {
    int idx = blockIdx.x * blockDim.x + threadIdx.x;
    if (idx >= NL0 * 32) return;
    int l = idx >> 5, i = idx & 31;
    float argf = (float)(2 * i) * (float)(-log(10000.0) / 64.0);
    float divf = (float)exp((double)argf);
    float angf = (float)l * divf;
    double ang = (double)angf;
    g_pe[l * ND + 2 * i]     = (float)sin(ang);
    g_pe[l * ND + 2 * i + 1] = (float)cos(ang);
}

// ---------------------------------------------------------------------------
// Repack c_w{s} (co, ci, kk):
//   row = kk*32 + ci/2, col = ((co&3)>>1)*64 + (co>>2)*4 + (co&1)*2 + (ci&1)
// Lane tx's 4 co x 1 ci-pair = two contiguous 16B chunks at tx*16B per half;
// LDS.128, conflict-free, (ci-even, ci-odd) adjacent for FFMA2.
// ---------------------------------------------------------------------------
__global__ void wt_kernel(const float* __restrict__ w1,
                          const float* __restrict__ w2,
                          const float* __restrict__ w3) {
    int idx = blockIdx.x * blockDim.x + threadIdx.x;
    if (idx >= 3 * 64 * 64 * 4) return;
    int s = idx / 16384;
    int rem = idx - s * 16384;          // rem = co*256 + ci*4 + kk
    int co = rem >> 8;
    int ci = (rem >> 2) & 63;
    int kk = rem & 3;
    const float* w = (s == 0) ? w1 : (s == 1) ? w2 : w3;
    int row = kk * 32 + (ci >> 1);
    int col = ((co & 3) >> 1) * 64 + (co >> 2) * 4 + (co & 1) * 2 + (ci & 1);
    g_wt[s][row][col] = w[rem];
}

// ---------------------------------------------------------------------------
// Compression stage: conv1d(64->64, k=4, s=2, p=1) -> tanh [-> LN over D].
// Persistent CTAs (1/SM), 512 threads = 16 warps/SM (4 per SMSP for latency
// hiding). Tile = 256 out positions x 64 channels; thread micro-tile 8 pos x
// 4 co, f32x2-packed over the ci reduction.
// Per (kk, ci-quad): 4 w-LDS.128 + 8 x-LDS.128 -> 64 FFMA2 (fma-pipe-bound).
// FUSE_FRONT: stage1 computes token-embedding conv + PE on the fly during the
// Xs fill (x is 2MB / L2-resident; no staged embedding round-trip).
// ---------------------------------------------------------------------------
// smem layout (floats):
#define OFF_XSL  0                       // 528: raw-x slice (fused only)
#define OFF_XS   528                     // 514*68 = 34952: input halo, stride 68
#define OFF_WS   (528 + 34952)           // 16384: stage weights (repacked)
#define OFF_BSM  (OFF_WS + 16384)
#define OFF_GSM  (OFF_BSM + 64)
#define OFF_LBSM (OFF_GSM + 64)
#define OFF_TW   (OFF_LBSM + 64)         // 384: token conv weights (fused only)
#define OFF_TB   (OFF_TW + 384)          // 64:  token conv bias
#define SMEM_FLOATS (OFF_TB + 64)        // 52504 floats = 210,016 B

template <bool HAS_LN, bool FUSE_FRONT>
__global__ void __launch_bounds__(512, 1)
stage_kernel(const float* __restrict__ in, float* __restrict__ out,
             const float* __restrict__ wt, const float* __restrict__ bias,
             const float* __restrict__ lng, const float* __restrict__ lnb,
             const float* __restrict__ pe,
             const float* __restrict__ tw3, const float* __restrict__ tb3,
             const float* __restrict__ tw5, const float* __restrict__ tb5,
             const float* __restrict__ tw7, const float* __restrict__ tb7,
             const float* __restrict__ tw9, const float* __restrict__ tb9,
             int Lin, int Lout, int numTiles) {
    extern __shared__ float smem[];
    float* xsl  = smem + OFF_XSL;
    float* Xs   = smem + OFF_XS;
    float* Ws   = smem + OFF_WS;
    float* bsm  = smem + OFF_BSM;
    float* gsm  = smem + OFF_GSM;
    float* lbsm = smem + OFF_LBSM;
    float* twsm = smem + OFF_TW;
    float* tbsm = smem + OFF_TB;

    int tid = threadIdx.x;
    {   // stage weights -> smem
        const float4* wt4 = (const float4*)wt;
        float4* Ws4 = (float4*)Ws;
        for (int i = tid; i < 4096; i += 512) Ws4[i] = wt4[i];
    }
    if (tid < 64) {
        bsm[tid] = bias[tid];
        if (HAS_LN) { gsm[tid] = lng[tid]; lbsm[tid] = lnb[tid]; }
    }
    if (FUSE_FRONT) {
        if (tid < 48)  twsm[tid]        = tw3[tid];
        if (tid < 80)  twsm[48  + tid]  = tw5[tid];
        if (tid < 112) twsm[128 + tid]  = tw7[tid];
        if (tid < 144) twsm[240 + tid]  = tw9[tid];
        if (tid < 64) {
            int g = tid & 3, j = tid >> 2;
            tbsm[tid] = (g == 0 ? tb3 : g == 1 ? tb5 : g == 2 ? tb7 : tb9)[j];
        }
    }
    __syncthreads();

    // fused-front per-thread token-conv weights (fill channel is tid&63)
    int   fc = tid & 63;
    float fw[9];
    float fb = 0.f;
    int   fpad = 0;
    if (FUSE_FRONT) {
        int fg = fc & 3, fj = fc >> 2;
        int fks = 3 + 2 * fg;
        fpad = fg + 1;
        int woff = (fg == 0 ? 0 : fg == 1 ? 48 : fg == 2 ? 128 : 240) + fj * fks;
#pragma unroll
        for (int k = 0; k < 9; ++k) fw[k] = (k < fks) ? twsm[woff + k] : 0.f;
        fb = tbsm[fc];
    }

    int tx = tid & 15, ty = tid >> 4;       // 16 x 32
    int co0 = tx * 4, p0 = ty * 8;          // 256 positions covered
    int tilesPerB = Lout >> 8;

    for (int tile = blockIdx.x; tile < numTiles; tile += gridDim.x) {
        int b = tile / tilesPerB;
        int t = tile - b * tilesPerB;
        int l0 = t << 8;
        int g0 = 2 * l0 - 1;

        __syncthreads();   // protect Xs/xsl against previous iteration's readers
        if (FUSE_FRONT) {
            const float* xb = in + (size_t)b * NL0;
            for (int i = tid; i < 528; i += 512) {
                int gl = g0 - 4 + i;
                xsl[i] = (gl >= 0 && gl < NL0) ? xb[gl] : 0.f;
            }
            __syncthreads();
            for (int i = tid; i < 514 * 64; i += 512) {
                int row = i >> 6;                 // channel = fc (tid&63) every iter
                int gg = g0 + row;
                float v = 0.f;
                if (gg >= 0 && gg < NL0) {
                    v = fb;
                    int base = row + 4 - fpad;
#pragma unroll
                    for (int k = 0; k < 9; ++k) v = fmaf(fw[k], xsl[base + k], v);
                    v += __ldg(pe + (size_t)gg * ND + fc);
                }
                Xs[row * 68 + fc] = v;
            }
        } else {
            const float* inb = in + (size_t)b * Lin * ND;
            for (int i = tid; i < 514 * 64; i += 512) {
                int row = i >> 6, cc = i & 63;
                int gg = g0 + row;
                Xs[row * 68 + cc] = (gg >= 0 && gg < Lin) ? inb[(size_t)gg * 64 + cc] : 0.f;
            }
        }
        __syncthreads();

        u64 acc[8][4];
#pragma unroll
        for (int j = 0; j < 8; ++j)
#pragma unroll
            for (int i = 0; i < 4; ++i) acc[j][i] = 0ull;

#pragma unroll 1
        for (int kk = 0; kk < 4; ++kk) {
            const float* xk = Xs + (2 * p0 + kk) * 68;
            const ulonglong2* wk = (const ulonglong2*)(Ws + kk * 4096) + tx;
#pragma unroll 2
            for (int cq = 0; cq < 16; ++cq) {
                const ulonglong2* wp = wk + cq * 64;
                ulonglong2 wA0 = wp[0];    // ci-pair A: co0,co1
                ulonglong2 wA1 = wp[16];   // ci-pair A: co2,co3
                ulonglong2 wB0 = wp[32];   // ci-pair B: co0,co1
                ulonglong2 wB1 = wp[48];   // ci-pair B: co2,co3
                const float* xq = xk + cq * 4;
#pragma unroll
                for (int j = 0; j < 8; ++j) {
                    ulonglong2 xv = *(const ulonglong2*)(xq + j * 136);
                    ffma2(acc[j][0], xv.x, wA0.x);
                    ffma2(acc[j][1], xv.x, wA0.y);
                    ffma2(acc[j][2], xv.x, wA1.x);
                    ffma2(acc[j][3], xv.x, wA1.y);
                    ffma2(acc[j][0], xv.y, wB0.x);
                    ffma2(acc[j][1], xv.y, wB0.y);
                    ffma2(acc[j][2], xv.y, wB1.x);
                    ffma2(acc[j][3], xv.y, wB1.y);
                }
            }
        }

        float* outb = out + ((size_t)b * Lout + l0) * ND;
#pragma unroll
        for (int j = 0; j < 8; ++j) {
            float t0 = tanhf(unpack_sum(acc[j][0]) + bsm[co0 + 0]);
            float t1 = tanhf(unpack_sum(acc[j][1]) + bsm[co0 + 1]);
            float t2 = tanhf(unpack_sum(acc[j][2]) + bsm[co0 + 2]);
            float t3 = tanhf(unpack_sum(acc[j][3]) + bsm[co0 + 3]);
            float4 o4;
            if (HAS_LN) {
                float s1 = t0 + t1 + t2 + t3;
                float s2 = t0 * t0 + t1 * t1 + t2 * t2 + t3 * t3;
#pragma unroll
                for (int o = 1; o < 16; o <<= 1) {
                    s1 += __shfl_xor_sync(0xffffffffu, s1, o);
                    s2 += __shfl_xor_sync(0xffffffffu, s2, o);
                }
                float m   = s1 * (1.f / 64.f);
                float v   = s2 * (1.f / 64.f) - m * m;
                float inv = 1.f / sqrtf(v + 1e-5f);
                o4.x = (t0 - m) * inv * gsm[co0 + 0] + lbsm[co0 + 0];
                o4.y = (t1 - m) * inv * gsm[co0 + 1] + lbsm[co0 + 1];
                o4.z = (t2 - m) * inv * gsm[co0 + 2] + lbsm[co0 + 2];
                o4.w = (t3 - m) * inv * gsm[co0 + 3] + lbsm[co0 + 3];
            } else {
                o4.x = t0; o4.y = t1; o4.z = t2; o4.w = t3;
            }
            *(float4*)(outb + (size_t)(p0 + j) * ND + co0) = o4;
        }
    }
}

extern "C" void kernel_launch(void* const* d_in, const int* in_sizes, int n_in,
                              void* d_out, int out_size) {
    const float* x   = (const float*)d_in[0];
    const float* tw3 = (const float*)d_in[1];
    const float* tb3 = (const float*)d_in[2];
    const float* tw5 = (const float*)d_in[3];
    const float* tb5 = (const float*)d_in[4];
    const float* tw7 = (const float*)d_in[5];
    const float* tb7 = (const float*)d_in[6];
    const float* tw9 = (const float*)d_in[7];
    const float* tb9 = (const float*)d_in[8];
    const float* cw1 = (const float*)d_in[9];
    const float* cb1 = (const float*)d_in[10];
    const float* cw2 = (const float*)d_in[11];
    const float* cb2 = (const float*)d_in[12];
    const float* cw3 = (const float*)d_in[13];
    const float* cb3 = (const float*)d_in[14];
    const float* lg1 = (const float*)d_in[15];
    const float* lb1 = (const float*)d_in[16];
    const float* lg2 = (const float*)d_in[17];
    const float* lb2 = (const float*)d_in[18];
    (void)in_sizes; (void)n_in; (void)out_size;

    void *pe_p, *wt_p, *h1_p, *h2_p;
    cudaGetSymbolAddress(&pe_p, g_pe);
    cudaGetSymbolAddress(&wt_p, g_wt);
    cudaGetSymbolAddress(&h1_p, g_h1);
    cudaGetSymbolAddress(&h2_p, g_h2);
    float* pe  = (float*)pe_p;
    float* h1  = (float*)h1_p;
    float* h2  = (float*)h2_p;
    float* wtb = (float*)wt_p;

    const int smemsz = SMEM_FLOATS * 4;   // 210,016 B -> 1 CTA/SM, 16 warps
    cudaFuncSetAttribute((const void*)stage_kernel<true, true>,
                         cudaFuncAttributeMaxDynamicSharedMemorySize, smemsz);
    cudaFuncSetAttribute((const void*)stage_kernel<true, false>,
                         cudaFuncAttributeMaxDynamicSharedMemorySize, smemsz);
    cudaFuncSetAttribute((const void*)stage_kernel<false, false>,
                         cudaFuncAttributeMaxDynamicSharedMemorySize, smemsz);

    pe_kernel<<<(NL0 * 32 + 255) / 256, 256>>>();
    wt_kernel<<<(3 * 64 * 64 * 4 + 255) / 256, 256>>>(cw1, cw2, cw3);

    // stage1: fused token-embedding + PE front-end, reads raw x
    stage_kernel<true, true><<<148, 512, smemsz>>>(
        x, h1, wtb + 0 * 128 * 128, cb1, lg1, lb1, pe,
        tw3, tb3, tw5, tb5, tw7, tb7, tw9, tb9,
        NL0, NL1, NB * (NL1 / 256));
    stage_kernel<true, false><<<148, 512, smemsz>>>(
        h1, h2, wtb + 1 * 128 * 128, cb2, lg2, lb2, pe,
        nullptr, nullptr, nullptr, nullptr, nullptr, nullptr, nullptr, nullptr,
        NL1, NL2, NB * (NL2 / 256));
    stage_kernel<false, false><<<148, 512, smemsz>>>(
        h2, (float*)d_out, wtb + 2 * 128 * 128, cb3, nullptr, nullptr, pe,
        nullptr, nullptr, nullptr, nullptr, nullptr, nullptr, nullptr, nullptr,
        NL2, NL3, NB * (NL3 / 256));
}

// round 8
// speedup vs baseline: 2.0096x; 1.7022x over previous
#include <cuda_runtime.h>
#include <cuda_bf16.h>
#include <math.h>
#include <stdint.h>

#define NB 128
#define ND 64
#define NL0 4096
#define NL1 2048
#define NL2 1024
#define NL3 512

// Scratch (static device allocations allowed; cudaMalloc is not)
__device__ float g_pe[NL0 * ND];                      // 1 MB positional table
__device__ __nv_bfloat16 g_wtb[3][2][64 * 264];       // W hi/lo planes, row stride 264 bf16 (528B)
__device__ float g_h1[(size_t)NB * NL1 * ND];         // 67 MB
__device__ float g_h2[(size_t)NB * NL2 * ND];         // 33.5 MB

__device__ __forceinline__ uint32_t smem_u32(const void* p) {
    uint32_t a;
    asm("{ .reg .u64 t; cvta.to.shared.u64 t, %1; cvt.u32.u64 %0, t; }" : "=r"(a) : "l"(p));
    return a;
}
__device__ __forceinline__ void ldsm4(uint32_t* r, uint32_t a) {
    asm volatile("ldmatrix.sync.aligned.m8n8.x4.shared.b16 {%0,%1,%2,%3}, [%4];"
                 : "=r"(r[0]), "=r"(r[1]), "=r"(r[2]), "=r"(r[3]) : "r"(a));
}
__device__ __forceinline__ void mma16816(float* c, const uint32_t* a, const uint32_t* b) {
    asm volatile("mma.sync.aligned.m16n8k16.row.col.f32.bf16.bf16.f32 "
                 "{%0,%1,%2,%3}, {%4,%5,%6,%7}, {%8,%9}, {%0,%1,%2,%3};"
                 : "+f"(c[0]), "+f"(c[1]), "+f"(c[2]), "+f"(c[3])
                 : "r"(a[0]), "r"(a[1]), "r"(a[2]), "r"(a[3]), "r"(b[0]), "r"(b[1]));
}

// ---------------------------------------------------------------------------
// Positional embedding table (double precision: matches the reference's fp32
// rounding chain; avoids sinf large-arg reduction error).
// ---------------------------------------------------------------------------
__global__ void pe_kernel() {
    int idx = blockIdx.x * blockDim.x + threadIdx.x;
    if (idx >= NL0 * 32) return;
    int l = idx >> 5, i = idx & 31;
    float argf = (float)(2 * i) * (float)(-log(10000.0) / 64.0);
    float divf = (float)exp((double)argf);
    float angf = (float)l * divf;
    double ang = (double)angf;
    g_pe[l * ND + 2 * i]     = (float)sin(ang);
    g_pe[l * ND + 2 * i + 1] = (float)cos(ang);
}

// ---------------------------------------------------------------------------
// Split conv weights (co, ci, kk) into bf16 hi/lo planes, W[co][k=kk*64+ci],
// row stride 264 bf16 (528B -> ldmatrix conflict-free: 528 ≡ 16 mod 32).
// ---------------------------------------------------------------------------
__global__ void wt_kernel(const float* __restrict__ w1,
                          const float* __restrict__ w2,
                          const float* __restrict__ w3) {
    int idx = blockIdx.x * blockDim.x + threadIdx.x;
    if (idx >= 3 * 64 * 64 * 4) return;
    int s = idx / 16384;
    int rem = idx - s * 16384;            // co*256 + ci*4 + kk
    int co = rem >> 8;
    int ci = (rem >> 2) & 63;
    int kk = rem & 3;
    const float* w = (s == 0) ? w1 : (s == 1) ? w2 : w3;
    float v = w[rem];
    __nv_bfloat16 hi = __float2bfloat16(v);
    __nv_bfloat16 lo = __float2bfloat16(v - __bfloat162float(hi));
    int off = co * 264 + kk * 64 + ci;
    g_wtb[s][0][off] = hi;
    g_wtb[s][1][off] = lo;
}

// ---------------------------------------------------------------------------
// Stage as mma.sync bf16 GEMM. Tile: D[256 pos, 64 co] = A[256, 256] x Wt,
// A[p][kk*64+ci] = X[2p-1+kk][ci] gathered by ldmatrix straight from the X
// halo (no im2col copy). 3-term hi/lo split, fp32 register accumulators.
// X smem: 514 rows, stride 144B, XOR-16 swizzle on (row&8) -> the stride-2
// ldmatrix row pattern (rows 2r+kk) is bank-conflict-free for every kk.
// 512 threads = 16 warps; warp w owns positions [16w, 16w+16).
// Epilogue in registers: tanh -> LN via 2 shfl_xor over the lane quad.
// ---------------------------------------------------------------------------
#define X_ROWS   514
#define X_STRIDE 144
#define SM_XHI   0
#define SM_XLO   (X_ROWS * X_STRIDE)                  // 74,016
#define SM_WHI   (2 * X_ROWS * X_STRIDE)              // 148,032
#define SM_WLO   (SM_WHI + 64 * 528)                  // 181,824
#define SM_F     (SM_WLO + 64 * 528)                  // 215,616 (float misc)
#define SMEM_BYTES (SM_F + 1168 * 4)                  // 220,288 B

template <bool HAS_LN, bool FUSE>
__global__ void __launch_bounds__(512, 1)
mma_stage(const float* __restrict__ in, float* __restrict__ out,
          const __nv_bfloat16* __restrict__ whi_g, const __nv_bfloat16* __restrict__ wlo_g,
          const float* __restrict__ bias, const float* __restrict__ lng,
          const float* __restrict__ lnb, const float* __restrict__ pe,
          const float* __restrict__ tw3, const float* __restrict__ tb3,
          const float* __restrict__ tw5, const float* __restrict__ tb5,
          const float* __restrict__ tw7, const float* __restrict__ tb7,
          const float* __restrict__ tw9, const float* __restrict__ tb9,
          int Lin, int Lout, int numTiles) {
    extern __shared__ char smem[];
    int tid = threadIdx.x, lane = tid & 31, wid = tid >> 5;

    // W planes -> smem (already in final row layout): 2112 uint4 per plane
    {
        const uint4* s0 = (const uint4*)whi_g;
        const uint4* s1 = (const uint4*)wlo_g;
        uint4* d0 = (uint4*)(smem + SM_WHI);
        uint4* d1 = (uint4*)(smem + SM_WLO);
        for (int i = tid; i < 2112; i += 512) { d0[i] = s0[i]; d1[i] = s1[i]; }
    }
    float* fm   = (float*)(smem + SM_F);
    float* bsm  = fm;
    float* gsm  = fm + 64;
    float* lbsm = fm + 128;
    float* tbsm = fm + 192;
    float* twsm = fm + 256;
    float* xsl  = fm + 640;
    if (tid < 64) {
        bsm[tid] = bias[tid];
        if (HAS_LN) { gsm[tid] = lng[tid]; lbsm[tid] = lnb[tid]; }
    }
    if (FUSE) {
        if (tid < 48)  twsm[tid]       = tw3[tid];
        if (tid < 80)  twsm[48 + tid]  = tw5[tid];
        if (tid < 112) twsm[128 + tid] = tw7[tid];
        if (tid < 144) twsm[240 + tid] = tw9[tid];
        if (tid < 64) {
            int g = tid & 3, j = tid >> 2;
            tbsm[tid] = (g == 0 ? tb3 : g == 1 ? tb5 : g == 2 ? tb7 : tb9)[j];
        }
    }
    __syncthreads();

    // fused-front token-conv weights (fill channel = tid&63)
    int ci = tid & 63;
    float fw[9]; float fb = 0.f; int fpad = 0;
    if (FUSE) {
        int fg = ci & 3, fj = ci >> 2;
        int fks = 3 + 2 * fg;
        fpad = fg + 1;
        int woff = (fg == 0 ? 0 : fg == 1 ? 48 : fg == 2 ? 128 : 240) + fj * fks;
#pragma unroll
        for (int k = 0; k < 9; ++k) fw[k] = (k < fks) ? twsm[woff + k] : 0.f;
        fb = tbsm[ci];
    }

    // ldmatrix lane geometry
    int warp_p0 = wid * 16;
    int arow   = lane & 15;
    int row2   = 2 * (warp_p0 + arow);                 // + kk at use
    int acib   = (lane >> 4) << 4;                     // +16B for k-high half
    int wrow   = (lane & 7) + ((lane >> 4) << 3);
    uint32_t wbyte = (uint32_t)(wrow * 528 + (((lane >> 3) & 1) << 4));
    uint32_t xhi_b = smem_u32(smem + SM_XHI);
    uint32_t xlo_b = smem_u32(smem + SM_XLO);
    uint32_t whi_b = smem_u32(smem + SM_WHI) + wbyte;
    uint32_t wlo_b = smem_u32(smem + SM_WLO) + wbyte;

    int tilesPerB = Lout >> 8;
    for (int tile = blockIdx.x; tile < numTiles; tile += gridDim.x) {
        int b = tile / tilesPerB;
        int t = tile - b * tilesPerB;
        int p0 = t << 8;
        int g0 = 2 * p0 - 1;

        __syncthreads();   // protect X/xsl against previous iteration's readers
        if (FUSE) {
            const float* xb = in + (size_t)b * NL0;
            for (int i = tid; i < 528; i += 512) {
                int gl = g0 - 4 + i;
                xsl[i] = (gl >= 0 && gl < NL0) ? xb[gl] : 0.f;
            }
            __syncthreads();
            for (int i = tid; i < X_ROWS * 64; i += 512) {
                int row = i >> 6;
                int gg = g0 + row;
                float v = 0.f;
                if (gg >= 0 && gg < NL0) {
                    v = fb;
                    int base = row + 4 - fpad;
#pragma unroll
                    for (int k = 0; k < 9; ++k) v = fmaf(fw[k], xsl[base + k], v);
                    v += __ldg(pe + (size_t)gg * ND + ci);
                }
                __nv_bfloat16 hi = __float2bfloat16(v);
                __nv_bfloat16 lo = __float2bfloat16(v - __bfloat162float(hi));
                uint32_t xo = (uint32_t)(row * X_STRIDE) + (uint32_t)((ci * 2) ^ ((row & 8) << 1));
                *(__nv_bfloat16*)(smem + SM_XHI + xo) = hi;
                *(__nv_bfloat16*)(smem + SM_XLO + xo) = lo;
            }
        } else {
            const float* inb = in + (size_t)b * Lin * ND;
            for (int i = tid; i < X_ROWS * 64; i += 512) {
                int row = i >> 6;
                int gg = g0 + row;
                float v = (gg >= 0 && gg < Lin) ? __ldg(inb + (size_t)gg * ND + ci) : 0.f;
                __nv_bfloat16 hi = __float2bfloat16(v);
                __nv_bfloat16 lo = __float2bfloat16(v - __bfloat162float(hi));
                uint32_t xo = (uint32_t)(row * X_STRIDE) + (uint32_t)((ci * 2) ^ ((row & 8) << 1));
                *(__nv_bfloat16*)(smem + SM_XHI + xo) = hi;
                *(__nv_bfloat16*)(smem + SM_XLO + xo) = lo;
            }
        }
        __syncthreads();

        float c[8][4];
#pragma unroll
        for (int n = 0; n < 8; ++n)
#pragma unroll
            for (int q = 0; q < 4; ++q) c[n][q] = 0.f;

#pragma unroll 2
        for (int ks = 0; ks < 16; ++ks) {
            int kk = ks >> 2;
            int xr = row2 + kk;
            uint32_t axo = (uint32_t)(xr * X_STRIDE) +
                           (uint32_t)((((ks & 3) << 5) + acib) ^ ((xr & 8) << 1));
            uint32_t ah[4], al[4], bh[16], bl[16];
            ldsm4(ah, xhi_b + axo);
            ldsm4(al, xlo_b + axo);
            uint32_t wko = (uint32_t)(ks << 5);
            ldsm4(bh + 0,  whi_b + wko);
            ldsm4(bh + 4,  whi_b + wko + 16 * 528);
            ldsm4(bh + 8,  whi_b + wko + 32 * 528);
            ldsm4(bh + 12, whi_b + wko + 48 * 528);
            ldsm4(bl + 0,  wlo_b + wko);
            ldsm4(bl + 4,  wlo_b + wko + 16 * 528);
            ldsm4(bl + 8,  wlo_b + wko + 32 * 528);
            ldsm4(bl + 12, wlo_b + wko + 48 * 528);
#pragma unroll
            for (int g = 0; g < 4; ++g) {
                mma16816(c[2 * g],     ah, bh + 4 * g);
                mma16816(c[2 * g + 1], ah, bh + 4 * g + 2);
                mma16816(c[2 * g],     al, bh + 4 * g);
                mma16816(c[2 * g + 1], al, bh + 4 * g + 2);
                mma16816(c[2 * g],     ah, bl + 4 * g);
                mma16816(c[2 * g + 1], ah, bl + 4 * g + 2);
            }
        }

        // ---- epilogue: rows (warp_p0 + lane/4) and +8; cols n*8 + 2*(lane&3) ----
        int r0 = warp_p0 + (lane >> 2);
        int colb = (lane & 3) * 2;
        float va[16], vb[16];
#pragma unroll
        for (int n = 0; n < 8; ++n) {
            int cn = n * 8 + colb;
            va[2 * n]     = tanhf(c[n][0] + bsm[cn]);
            va[2 * n + 1] = tanhf(c[n][1] + bsm[cn + 1]);
            vb[2 * n]     = tanhf(c[n][2] + bsm[cn]);
            vb[2 * n + 1] = tanhf(c[n][3] + bsm[cn + 1]);
        }
        if (HAS_LN) {
            float s1a = 0.f, s2a = 0.f, s1b = 0.f, s2b = 0.f;
#pragma unroll
            for (int q = 0; q < 16; ++q) {
                s1a += va[q]; s2a += va[q] * va[q];
                s1b += vb[q]; s2b += vb[q] * vb[q];
            }
#pragma unroll
            for (int o = 1; o < 4; o <<= 1) {
                s1a += __shfl_xor_sync(0xffffffffu, s1a, o);
                s2a += __shfl_xor_sync(0xffffffffu, s2a, o);
                s1b += __shfl_xor_sync(0xffffffffu, s1b, o);
                s2b += __shfl_xor_sync(0xffffffffu, s2b, o);
            }
            float ma  = s1a * (1.f / 64.f), mb = s1b * (1.f / 64.f);
            float ia  = rsqrtf(s2a * (1.f / 64.f) - ma * ma + 1e-5f);
            float ib  = rsqrtf(s2b * (1.f / 64.f) - mb * mb + 1e-5f);
            // match reference 1/sqrt numerics closely enough (rsqrt ~2^-22 rel)
            ia = 1.f / sqrtf(s2a * (1.f / 64.f) - ma * ma + 1e-5f);
            ib = 1.f / sqrtf(s2b * (1.f / 64.f) - mb * mb + 1e-5f);
#pragma unroll
            for (int n = 0; n < 8; ++n) {
                int cn = n * 8 + colb;
                va[2 * n]     = (va[2 * n]     - ma) * ia * gsm[cn]     + lbsm[cn];
                va[2 * n + 1] = (va[2 * n + 1] - ma) * ia * gsm[cn + 1] + lbsm[cn + 1];
                vb[2 * n]     = (vb[2 * n]     - mb) * ib * gsm[cn]     + lbsm[cn];
                vb[2 * n + 1] = (vb[2 * n + 1] - mb) * ib * gsm[cn + 1] + lbsm[cn + 1];
            }
        }
        float* oa = out + ((size_t)b * Lout + p0 + r0) * ND + colb;
        float* ob = out + ((size_t)b * Lout + p0 + r0 + 8) * ND + colb;
#pragma unroll
        for (int n = 0; n < 8; ++n) {
            *(float2*)(oa + n * 8) = make_float2(va[2 * n], va[2 * n + 1]);
            *(float2*)(ob + n * 8) = make_float2(vb[2 * n], vb[2 * n + 1]);
        }
    }
}

extern "C" void kernel_launch(void* const* d_in, const int* in_sizes, int n_in,
                              void* d_out, int out_size) {
    const float* x   = (const float*)d_in[0];
    const float* tw3 = (const float*)d_in[1];
    const float* tb3 = (const float*)d_in[2];
    const float* tw5 = (const float*)d_in[3];
    const float* tb5 = (const float*)d_in[4];
    const float* tw7 = (const float*)d_in[5];
    const float* tb7 = (const float*)d_in[6];
    const float* tw9 = (const float*)d_in[7];
    const float* tb9 = (const float*)d_in[8];
    const float* cw1 = (const float*)d_in[9];
    const float* cb1 = (const float*)d_in[10];
    const float* cw2 = (const float*)d_in[11];
    const float* cb2 = (const float*)d_in[12];
    const float* cw3 = (const float*)d_in[13];
    const float* cb3 = (const float*)d_in[14];
    const float* lg1 = (const float*)d_in[15];
    const float* lb1 = (const float*)d_in[16];
    const float* lg2 = (const float*)d_in[17];
    const float* lb2 = (const float*)d_in[18];
    (void)in_sizes; (void)n_in; (void)out_size;

    void *pe_p, *wt_p, *h1_p, *h2_p;
    cudaGetSymbolAddress(&pe_p, g_pe);
    cudaGetSymbolAddress(&wt_p, g_wtb);
    cudaGetSymbolAddress(&h1_p, g_h1);
    cudaGetSymbolAddress(&h2_p, g_h2);
    float* pe = (float*)pe_p;
    float* h1 = (float*)h1_p;
    float* h2 = (float*)h2_p;
    __nv_bfloat16* wtb = (__nv_bfloat16*)wt_p;   // [3][2][64*264]

    cudaFuncSetAttribute((const void*)mma_stage<true, true>,
                         cudaFuncAttributeMaxDynamicSharedMemorySize, SMEM_BYTES);
    cudaFuncSetAttribute((const void*)mma_stage<true, false>,
                         cudaFuncAttributeMaxDynamicSharedMemorySize, SMEM_BYTES);
    cudaFuncSetAttribute((const void*)mma_stage<false, false>,
                         cudaFuncAttributeMaxDynamicSharedMemorySize, SMEM_BYTES);

    pe_kernel<<<(NL0 * 32 + 255) / 256, 256>>>();
    wt_kernel<<<(3 * 64 * 64 * 4 + 255) / 256, 256>>>(cw1, cw2, cw3);

    const int PL = 64 * 264;   // bf16 elements per plane
    // stage1: fused token-embedding + PE front, reads raw x
    mma_stage<true, true><<<148, 512, SMEM_BYTES>>>(
        x, h1, wtb + (0 * 2 + 0) * PL, wtb + (0 * 2 + 1) * PL, cb1, lg1, lb1, pe,
        tw3, tb3, tw5, tb5, tw7, tb7, tw9, tb9,
        NL0, NL1, NB * (NL1 / 256));
    mma_stage<true, false><<<148, 512, SMEM_BYTES>>>(
        h1, h2, wtb + (1 * 2 + 0) * PL, wtb + (1 * 2 + 1) * PL, cb2, lg2, lb2, pe,
        nullptr, nullptr, nullptr, nullptr, nullptr, nullptr, nullptr, nullptr,
        NL1, NL2, NB * (NL2 / 256));
    mma_stage<false, false><<<148, 512, SMEM_BYTES>>>(
        h2, (float*)d_out, wtb + (2 * 2 + 0) * PL, wtb + (2 * 2 + 1) * PL, cb3, nullptr, nullptr, pe,
        nullptr, nullptr, nullptr, nullptr, nullptr, nullptr, nullptr, nullptr,
        NL2, NL3, NB * (NL3 / 256));
}

// round 9
// speedup vs baseline: 2.2467x; 1.1180x over previous
#include <cuda_runtime.h>
#include <cuda_bf16.h>
#include <math.h>
#include <stdint.h>

#define NB 128
#define ND 64
#define NL0 4096
#define NL1 2048
#define NL2 1024
#define NL3 512

// Scratch (static device allocations allowed; cudaMalloc is not)
__device__ float g_pe[NL0 * ND];                         // 1 MB positional table
__device__ __nv_bfloat16 g_wtb[3][2][64 * 264];          // W hi/lo planes, row stride 264 bf16 (528B)
__device__ __nv_bfloat16 g_h1b[2][(size_t)NB * NL1 * ND]; // h1 as bf16 hi/lo planes (33.5 MB each)
__device__ __nv_bfloat16 g_h2b[2][(size_t)NB * NL2 * ND]; // h2 as bf16 hi/lo planes

__device__ __forceinline__ uint32_t smem_u32(const void* p) {
    uint32_t a;
    asm("{ .reg .u64 t; cvta.to.shared.u64 t, %1; cvt.u32.u64 %0, t; }" : "=r"(a) : "l"(p));
    return a;
}
__device__ __forceinline__ void ldsm4(uint32_t* r, uint32_t a) {
    asm volatile("ldmatrix.sync.aligned.m8n8.x4.shared.b16 {%0,%1,%2,%3}, [%4];"
                 : "=r"(r[0]), "=r"(r[1]), "=r"(r[2]), "=r"(r[3]) : "r"(a));
}
__device__ __forceinline__ void mma16816(float* c, const uint32_t* a, const uint32_t* b) {
    asm volatile("mma.sync.aligned.m16n8k16.row.col.f32.bf16.bf16.f32 "
                 "{%0,%1,%2,%3}, {%4,%5,%6,%7}, {%8,%9}, {%0,%1,%2,%3};"
                 : "+f"(c[0]), "+f"(c[1]), "+f"(c[2]), "+f"(c[3])
                 : "r"(a[0]), "r"(a[1]), "r"(a[2]), "r"(a[3]), "r"(b[0]), "r"(b[1]));
}

// ---------------------------------------------------------------------------
// Positional embedding table (double precision: matches the reference's fp32
// rounding chain; avoids sinf large-arg reduction error).
// ---------------------------------------------------------------------------
__global__ void pe_kernel() {
    int idx = blockIdx.x * blockDim.x + threadIdx.x;
    if (idx >= NL0 * 32) return;
    int l = idx >> 5, i = idx & 31;
    float argf = (float)(2 * i) * (float)(-log(10000.0) / 64.0);
    float divf = (float)exp((double)argf);
    float angf = (float)l * divf;
    double ang = (double)angf;
    g_pe[l * ND + 2 * i]     = (float)sin(ang);
    g_pe[l * ND + 2 * i + 1] = (float)cos(ang);
}

// ---------------------------------------------------------------------------
// Split conv weights (co, ci, kk) into bf16 hi/lo planes, W[co][k=kk*64+ci],
// row stride 264 bf16 (528B -> ldmatrix conflict-free: 528 ≡ 16 mod 32).
// ---------------------------------------------------------------------------
__global__ void wt_kernel(const float* __restrict__ w1,
                          const float* __restrict__ w2,
                          const float* __restrict__ w3) {
    int idx = blockIdx.x * blockDim.x + threadIdx.x;
    if (idx >= 3 * 64 * 64 * 4) return;
    int s = idx / 16384;
    int rem = idx - s * 16384;            // co*256 + ci*4 + kk
    int co = rem >> 8;
    int ci = (rem >> 2) & 63;
    int kk = rem & 3;
    const float* w = (s == 0) ? w1 : (s == 1) ? w2 : w3;
    float v = w[rem];
    __nv_bfloat16 hi = __float2bfloat16(v);
    __nv_bfloat16 lo = __float2bfloat16(v - __bfloat162float(hi));
    int off = co * 264 + kk * 64 + ci;
    g_wtb[s][0][off] = hi;
    g_wtb[s][1][off] = lo;
}

// ---------------------------------------------------------------------------
// Stage as mma.sync bf16 GEMM. Tile: D[256 pos, 64 co] = A[256, 256] x Wt,
// A[p][kk*64+ci] = X[2p-1+kk][ci] gathered by ldmatrix straight from the X
// halo (no im2col copy). 3-term hi/lo split, fp32 register accumulators.
// X smem: 514 rows, stride 144B, XOR-16 swizzle on (row&8) -> stride-2
// ldmatrix row pattern conflict-free for every kk.
// Inter-stage handoff is bf16 hi/lo PLANES in gmem: the epilogue performs the
// split (values already in registers); the consumer fill is a pure uint4 copy.
// 512 threads = 16 warps; warp w owns positions [16w, 16w+16).
// ---------------------------------------------------------------------------
#define X_ROWS   514
#define X_STRIDE 144
#define SM_XHI   0
#define SM_XLO   (X_ROWS * X_STRIDE)                  // 74,016
#define SM_WHI   (2 * X_ROWS * X_STRIDE)              // 148,032
#define SM_WLO   (SM_WHI + 64 * 528)                  // 181,824
#define SM_F     (SM_WLO + 64 * 528)                  // 215,616 (float misc)
#define SMEM_BYTES (SM_F + 1168 * 4)                  // 220,288 B

template <bool HAS_LN, bool FUSE>
__global__ void __launch_bounds__(512, 1)
mma_stage(const float* __restrict__ inf,
          const __nv_bfloat16* __restrict__ inhi, const __nv_bfloat16* __restrict__ inlo,
          float* __restrict__ outf,
          __nv_bfloat16* __restrict__ outhi, __nv_bfloat16* __restrict__ outlo,
          const __nv_bfloat16* __restrict__ whi_g, const __nv_bfloat16* __restrict__ wlo_g,
          const float* __restrict__ bias, const float* __restrict__ lng,
          const float* __restrict__ lnb, const float* __restrict__ pe,
          const float* __restrict__ tw3, const float* __restrict__ tb3,
          const float* __restrict__ tw5, const float* __restrict__ tb5,
          const float* __restrict__ tw7, const float* __restrict__ tb7,
          const float* __restrict__ tw9, const float* __restrict__ tb9,
          int Lin, int Lout, int numTiles) {
    extern __shared__ char smem[];
    int tid = threadIdx.x, lane = tid & 31, wid = tid >> 5;

    // W planes -> smem (already in final row layout): 2112 uint4 per plane
    {
        const uint4* s0 = (const uint4*)whi_g;
        const uint4* s1 = (const uint4*)wlo_g;
        uint4* d0 = (uint4*)(smem + SM_WHI);
        uint4* d1 = (uint4*)(smem + SM_WLO);
        for (int i = tid; i < 2112; i += 512) { d0[i] = s0[i]; d1[i] = s1[i]; }
    }
    float* fm   = (float*)(smem + SM_F);
    float* bsm  = fm;
    float* gsm  = fm + 64;
    float* lbsm = fm + 128;
    float* tbsm = fm + 192;
    float* twsm = fm + 256;
    float* xsl  = fm + 640;
    if (tid < 64) {
        bsm[tid] = bias[tid];
        if (HAS_LN) { gsm[tid] = lng[tid]; lbsm[tid] = lnb[tid]; }
    }
    if (FUSE) {
        if (tid < 48)  twsm[tid]       = tw3[tid];
        if (tid < 80)  twsm[48 + tid]  = tw5[tid];
        if (tid < 112) twsm[128 + tid] = tw7[tid];
        if (tid < 144) twsm[240 + tid] = tw9[tid];
        if (tid < 64) {
            int g = tid & 3, j = tid >> 2;
            tbsm[tid] = (g == 0 ? tb3 : g == 1 ? tb5 : g == 2 ? tb7 : tb9)[j];
        }
    }
    __syncthreads();

    // fused-front token-conv weights (fill channel = tid&63)
    int ci = tid & 63;
    float fw[9]; float fb = 0.f; int fpad = 0;
    if (FUSE) {
        int fg = ci & 3, fj = ci >> 2;
        int fks = 3 + 2 * fg;
        fpad = fg + 1;
        int woff = (fg == 0 ? 0 : fg == 1 ? 48 : fg == 2 ? 128 : 240) + fj * fks;
#pragma unroll
        for (int k = 0; k < 9; ++k) fw[k] = (k < fks) ? twsm[woff + k] : 0.f;
        fb = tbsm[ci];
    }

    // ldmatrix lane geometry
    int warp_p0 = wid * 16;
    int arow   = lane & 15;
    int row2   = 2 * (warp_p0 + arow);                 // + kk at use
    int acib   = (lane >> 4) << 4;                     // +16B for k-high half
    int wrow   = (lane & 7) + ((lane >> 4) << 3);
    uint32_t wbyte = (uint32_t)(wrow * 528 + (((lane >> 3) & 1) << 4));
    uint32_t xhi_b = smem_u32(smem + SM_XHI);
    uint32_t xlo_b = smem_u32(smem + SM_XLO);
    uint32_t whi_b = smem_u32(smem + SM_WHI) + wbyte;
    uint32_t wlo_b = smem_u32(smem + SM_WLO) + wbyte;

    int tilesPerB = Lout >> 8;
    for (int tile = blockIdx.x; tile < numTiles; tile += gridDim.x) {
        int b = tile / tilesPerB;
        int t = tile - b * tilesPerB;
        int p0 = t << 8;
        int g0 = 2 * p0 - 1;

        __syncthreads();   // protect X/xsl against previous iteration's readers
        if (FUSE) {
            const float* xb = inf + (size_t)b * NL0;
            for (int i = tid; i < 528; i += 512) {
                int gl = g0 - 4 + i;
                xsl[i] = (gl >= 0 && gl < NL0) ? xb[gl] : 0.f;
            }
            __syncthreads();
            for (int i = tid; i < X_ROWS * 64; i += 512) {
                int row = i >> 6;
                int gg = g0 + row;
                float v = 0.f;
                if (gg >= 0 && gg < NL0) {
                    v = fb;
                    int base = row + 4 - fpad;
#pragma unroll
                    for (int k = 0; k < 9; ++k) v = fmaf(fw[k], xsl[base + k], v);
                    v += __ldg(pe + (size_t)gg * ND + ci);
                }
                __nv_bfloat16 hi = __float2bfloat16(v);
                __nv_bfloat16 lo = __float2bfloat16(v - __bfloat162float(hi));
                uint32_t xo = (uint32_t)(row * X_STRIDE) + (uint32_t)((ci * 2) ^ ((row & 8) << 1));
                *(__nv_bfloat16*)(smem + SM_XHI + xo) = hi;
                *(__nv_bfloat16*)(smem + SM_XLO + xo) = lo;
            }
        } else {
            // pure vectorized copy: input already split into bf16 hi/lo planes
            const __nv_bfloat16* ihb = inhi + (size_t)b * Lin * ND;
            const __nv_bfloat16* ilb = inlo + (size_t)b * Lin * ND;
            const uint4 z4 = make_uint4(0u, 0u, 0u, 0u);
            for (int i = tid; i < X_ROWS * 8; i += 512) {
                int row = i >> 3;
                int cb  = (i & 7) << 3;                // ci block of 8
                int gg  = g0 + row;
                uint4 vh = z4, vl = z4;
                if (gg >= 0 && gg < Lin) {
                    size_t go = (size_t)gg * ND + cb;
                    vh = *(const uint4*)(ihb + go);
                    vl = *(const uint4*)(ilb + go);
                }
                uint32_t xo = (uint32_t)(row * X_STRIDE) + (uint32_t)((cb * 2) ^ ((row & 8) << 1));
                *(uint4*)(smem + SM_XHI + xo) = vh;
                *(uint4*)(smem + SM_XLO + xo) = vl;
            }
        }
        __syncthreads();

        float c[8][4];
#pragma unroll
        for (int n = 0; n < 8; ++n)
#pragma unroll
            for (int q = 0; q < 4; ++q) c[n][q] = 0.f;

#pragma unroll 2
        for (int ks = 0; ks < 16; ++ks) {
            int kk = ks >> 2;
            int xr = row2 + kk;
            uint32_t axo = (uint32_t)(xr * X_STRIDE) +
                           (uint32_t)((((ks & 3) << 5) + acib) ^ ((xr & 8) << 1));
            uint32_t ah[4], al[4], bh[16], bl[16];
            ldsm4(ah, xhi_b + axo);
            ldsm4(al, xlo_b + axo);
            uint32_t wko = (uint32_t)(ks << 5);
            ldsm4(bh + 0,  whi_b + wko);
            ldsm4(bh + 4,  whi_b + wko + 16 * 528);
            ldsm4(bh + 8,  whi_b + wko + 32 * 528);
            ldsm4(bh + 12, whi_b + wko + 48 * 528);
            ldsm4(bl + 0,  wlo_b + wko);
            ldsm4(bl + 4,  wlo_b + wko + 16 * 528);
            ldsm4(bl + 8,  wlo_b + wko + 32 * 528);
            ldsm4(bl + 12, wlo_b + wko + 48 * 528);
#pragma unroll
            for (int g = 0; g < 4; ++g) {
                mma16816(c[2 * g],     ah, bh + 4 * g);
                mma16816(c[2 * g + 1], ah, bh + 4 * g + 2);
                mma16816(c[2 * g],     al, bh + 4 * g);
                mma16816(c[2 * g + 1], al, bh + 4 * g + 2);
                mma16816(c[2 * g],     ah, bl + 4 * g);
                mma16816(c[2 * g + 1], ah, bl + 4 * g + 2);
            }
        }

        // ---- epilogue: rows (warp_p0 + lane/4) and +8; cols n*8 + 2*(lane&3) ----
        int r0 = warp_p0 + (lane >> 2);
        int colb = (lane & 3) * 2;
        float va[16], vb[16];
#pragma unroll
        for (int n = 0; n < 8; ++n) {
            int cn = n * 8 + colb;
            va[2 * n]     = tanhf(c[n][0] + bsm[cn]);
            va[2 * n + 1] = tanhf(c[n][1] + bsm[cn + 1]);
            vb[2 * n]     = tanhf(c[n][2] + bsm[cn]);
            vb[2 * n + 1] = tanhf(c[n][3] + bsm[cn + 1]);
        }
        if (HAS_LN) {
            float s1a = 0.f, s2a = 0.f, s1b = 0.f, s2b = 0.f;
#pragma unroll
            for (int q = 0; q < 16; ++q) {
                s1a += va[q]; s2a += va[q] * va[q];
                s1b += vb[q]; s2b += vb[q] * vb[q];
            }
#pragma unroll
            for (int o = 1; o < 4; o <<= 1) {
                s1a += __shfl_xor_sync(0xffffffffu, s1a, o);
                s2a += __shfl_xor_sync(0xffffffffu, s2a, o);
                s1b += __shfl_xor_sync(0xffffffffu, s1b, o);
                s2b += __shfl_xor_sync(0xffffffffu, s2b, o);
            }
            float ma = s1a * (1.f / 64.f), mb = s1b * (1.f / 64.f);
            float ia = 1.f / sqrtf(s2a * (1.f / 64.f) - ma * ma + 1e-5f);
            float ib = 1.f / sqrtf(s2b * (1.f / 64.f) - mb * mb + 1e-5f);
            // LN stages write bf16 hi/lo planes (split done here, once)
            size_t rowa = (size_t)b * Lout + p0 + r0;
            __nv_bfloat16* oha = outhi + rowa * ND + colb;
            __nv_bfloat16* ola = outlo + rowa * ND + colb;
            __nv_bfloat16* ohb = oha + 8 * ND;
            __nv_bfloat16* olb = ola + 8 * ND;
#pragma unroll
            for (int n = 0; n < 8; ++n) {
                int cn = n * 8 + colb;
                float a0 = (va[2 * n]     - ma) * ia * gsm[cn]     + lbsm[cn];
                float a1 = (va[2 * n + 1] - ma) * ia * gsm[cn + 1] + lbsm[cn + 1];
                float b0 = (vb[2 * n]     - mb) * ib * gsm[cn]     + lbsm[cn];
                float b1 = (vb[2 * n + 1] - mb) * ib * gsm[cn + 1] + lbsm[cn + 1];
                __nv_bfloat16 h0 = __float2bfloat16(a0);
                __nv_bfloat16 h1 = __float2bfloat16(a1);
                __nv_bfloat16 h2 = __float2bfloat16(b0);
                __nv_bfloat16 h3 = __float2bfloat16(b1);
                *(__nv_bfloat162*)(oha + n * 8) = __nv_bfloat162(h0, h1);
                *(__nv_bfloat162*)(ohb + n * 8) = __nv_bfloat162(h2, h3);
                *(__nv_bfloat162*)(ola + n * 8) = __nv_bfloat162(
                    __float2bfloat16(a0 - __bfloat162float(h0)),
                    __float2bfloat16(a1 - __bfloat162float(h1)));
                *(__nv_bfloat162*)(olb + n * 8) = __nv_bfloat162(
                    __float2bfloat16(b0 - __bfloat162float(h2)),
                    __float2bfloat16(b1 - __bfloat162float(h3)));
            }
        } else {
            float* oa = outf + ((size_t)b * Lout + p0 + r0) * ND + colb;
            float* ob = oa + 8 * ND;
#pragma unroll
            for (int n = 0; n < 8; ++n) {
                *(float2*)(oa + n * 8) = make_float2(va[2 * n], va[2 * n + 1]);
                *(float2*)(ob + n * 8) = make_float2(vb[2 * n], vb[2 * n + 1]);
            }
        }
    }
}

extern "C" void kernel_launch(void* const* d_in, const int* in_sizes, int n_in,
                              void* d_out, int out_size) {
    const float* x   = (const float*)d_in[0];
    const float* tw3 = (const float*)d_in[1];
    const float* tb3 = (const float*)d_in[2];
    const float* tw5 = (const float*)d_in[3];
    const float* tb5 = (const float*)d_in[4];
    const float* tw7 = (const float*)d_in[5];
    const float* tb7 = (const float*)d_in[6];
    const float* tw9 = (const float*)d_in[7];
    const float* tb9 = (const float*)d_in[8];
    const float* cw1 = (const float*)d_in[9];
    const float* cb1 = (const float*)d_in[10];
    const float* cw2 = (const float*)d_in[11];
    const float* cb2 = (const float*)d_in[12];
    const float* cw3 = (const float*)d_in[13];
    const float* cb3 = (const float*)d_in[14];
    const float* lg1 = (const float*)d_in[15];
    const float* lb1 = (const float*)d_in[16];
    const float* lg2 = (const float*)d_in[17];
    const float* lb2 = (const float*)d_in[18];
    (void)in_sizes; (void)n_in; (void)out_size;

    void *pe_p, *wt_p, *h1_p, *h2_p;
    cudaGetSymbolAddress(&pe_p, g_pe);
    cudaGetSymbolAddress(&wt_p, g_wtb);
    cudaGetSymbolAddress(&h1_p, g_h1b);
    cudaGetSymbolAddress(&h2_p, g_h2b);
    float* pe = (float*)pe_p;
    __nv_bfloat16* wtb = (__nv_bfloat16*)wt_p;   // [3][2][64*264]
    __nv_bfloat16* h1hi = (__nv_bfloat16*)h1_p;
    __nv_bfloat16* h1lo = h1hi + (size_t)NB * NL1 * ND;
    __nv_bfloat16* h2hi = (__nv_bfloat16*)h2_p;
    __nv_bfloat16* h2lo = h2hi + (size_t)NB * NL2 * ND;

    cudaFuncSetAttribute((const void*)mma_stage<true, true>,
                         cudaFuncAttributeMaxDynamicSharedMemorySize, SMEM_BYTES);
    cudaFuncSetAttribute((const void*)mma_stage<true, false>,
                         cudaFuncAttributeMaxDynamicSharedMemorySize, SMEM_BYTES);
    cudaFuncSetAttribute((const void*)mma_stage<false, false>,
                         cudaFuncAttributeMaxDynamicSharedMemorySize, SMEM_BYTES);

    pe_kernel<<<(NL0 * 32 + 255) / 256, 256>>>();
    wt_kernel<<<(3 * 64 * 64 * 4 + 255) / 256, 256>>>(cw1, cw2, cw3);

    const int PL = 64 * 264;   // bf16 elements per W plane
    // stage1: fused token-embedding + PE front, reads raw x, writes bf16 planes
    mma_stage<true, true><<<148, 512, SMEM_BYTES>>>(
        x, nullptr, nullptr, nullptr, h1hi, h1lo,
        wtb + 0 * 2 * PL, wtb + (0 * 2 + 1) * PL, cb1, lg1, lb1, pe,
        tw3, tb3, tw5, tb5, tw7, tb7, tw9, tb9,
        NL0, NL1, NB * (NL1 / 256));
    mma_stage<true, false><<<148, 512, SMEM_BYTES>>>(
        nullptr, h1hi, h1lo, nullptr, h2hi, h2lo,
        wtb + 1 * 2 * PL, wtb + (1 * 2 + 1) * PL, cb2, lg2, lb2, pe,
        nullptr, nullptr, nullptr, nullptr, nullptr, nullptr, nullptr, nullptr,
        NL1, NL2, NB * (NL2 / 256));
    mma_stage<false, false><<<148, 512, SMEM_BYTES>>>(
        nullptr, h2hi, h2lo, (float*)d_out, nullptr, nullptr,
        wtb + 2 * 2 * PL, wtb + (2 * 2 + 1) * PL, cb3, nullptr, nullptr, pe,
        nullptr, nullptr, nullptr, nullptr, nullptr, nullptr, nullptr, nullptr,
        NL2, NL3, NB * (NL3 / 256));
}